// round 15
// baseline (speedup 1.0000x reference)
#include <cuda_runtime.h>
#include <cuda_bf16.h>
#include <cstdint>

#define BATCH 4
#define CCH   256
#define DQK   32
#define NTOK  4096

__device__ __nv_bfloat16 g_q[BATCH * NTOK * DQK];
__device__ __nv_bfloat16 g_k[BATCH * NTOK * DQK];
__device__ __nv_bfloat16 g_v[BATCH * NTOK * CCH];   // token-major [B,N,C]

__device__ __forceinline__ uint32_t smem_u32(const void* p) {
    return (uint32_t)__cvta_generic_to_shared(p);
}
__device__ __forceinline__ void cp16(uint32_t dst, const void* src) {
    asm volatile("cp.async.cg.shared.global [%0], [%1], 16;\n" :: "r"(dst), "l"(src));
}
__device__ __forceinline__ void cp_commit() { asm volatile("cp.async.commit_group;\n"); }
template <int N> __device__ __forceinline__ void cp_wait() {
    asm volatile("cp.async.wait_group %0;\n" :: "n"(N));
}
__device__ __forceinline__ void ldsm_x4(uint32_t* r, uint32_t a) {
    asm volatile("ldmatrix.sync.aligned.m8n8.x4.shared.b16 {%0,%1,%2,%3}, [%4];\n"
                 : "=r"(r[0]), "=r"(r[1]), "=r"(r[2]), "=r"(r[3]) : "r"(a));
}
__device__ __forceinline__ void ldsm_x4_t(uint32_t* r, uint32_t a) {
    asm volatile("ldmatrix.sync.aligned.m8n8.x4.trans.shared.b16 {%0,%1,%2,%3}, [%4];\n"
                 : "=r"(r[0]), "=r"(r[1]), "=r"(r[2]), "=r"(r[3]) : "r"(a));
}
__device__ __forceinline__ void mma_bf16(float* c, const uint32_t* a, const uint32_t* b) {
    asm volatile(
        "mma.sync.aligned.m16n8k16.row.col.f32.bf16.bf16.f32 "
        "{%0,%1,%2,%3}, {%4,%5,%6,%7}, {%8,%9}, {%0,%1,%2,%3};\n"
        : "+f"(c[0]), "+f"(c[1]), "+f"(c[2]), "+f"(c[3])
        : "r"(a[0]), "r"(a[1]), "r"(a[2]), "r"(a[3]), "r"(b[0]), "r"(b[1]));
}
__device__ __forceinline__ uint32_t packbf(float a, float b) {
    __nv_bfloat162 h = __floats2bfloat162_rn(a, b);
    return reinterpret_cast<uint32_t&>(h);
}
__device__ __forceinline__ float ex2f(float x) {
    float y; asm("ex2.approx.ftz.f32 %0, %1;" : "=f"(y) : "f"(x)); return y;
}

// ===================== projection kernel (R13) =====================
#define PROJ_SMEM (32768 + 32768)

__global__ void __launch_bounds__(256, 2)
proj_kernel(const float* __restrict__ zin, const float* __restrict__ xin,
            const float* __restrict__ yin,
            const float* __restrict__ Wq, const float* __restrict__ bq,
            const float* __restrict__ Wk, const float* __restrict__ bk,
            const float* __restrict__ Wv, const float* __restrict__ bv) {
    extern __shared__ char smem[];
    char* sA = smem;            // [c=256][128B] bf16 swizzled
    char* sW = smem + 32768;    // 2 x [d=32][512B] bf16 swizzled

    const int sel = blockIdx.z, b = blockIdx.y, n0 = blockIdx.x * 64;
    const int tid = threadIdx.x, l = tid & 31, wid = tid >> 5;
    const int wr = wid >> 1, wc = wid & 1;

    const float* src  = (sel == 0) ? xin : ((sel == 1) ? yin : zin);
    const float* W    = (sel == 0) ? Wq  : ((sel == 1) ? Wk  : Wv);
    const float* bias = (sel == 0) ? bq  : ((sel == 1) ? bk  : bv);
    __nv_bfloat16* dst = (sel == 0) ? g_q : ((sel == 1) ? g_k : g_v);
    const int dstw    = (sel == 2) ? CCH : DQK;
    const int nchunks = (sel == 2) ? 8 : 1;
    const float osc   = (sel == 0) ? 1.44269504f : 1.0f;

    const int wcq = tid & 63;

    float4 wreg[8];
#pragma unroll
    for (int j = 0; j < 8; ++j)
        wreg[j] = *(const float4*)(W + (size_t)(j * 4 + (tid >> 6)) * CCH + wcq * 4);

#pragma unroll
    for (int j = 0; j < 16; ++j) {
        int id = j * 256 + tid;
        int c = id >> 4, nq = id & 15;
        float4 f = *(const float4*)(src + ((size_t)(b * CCH + c) * NTOK + n0 + nq * 4));
        int nb = nq * 8;
        int phys = c * 128 + ((((nb & ~15) ^ ((c & 7) << 4))) | (nb & 15));
        *(__nv_bfloat162*)(sA + phys)     = __floats2bfloat162_rn(f.x, f.y);
        *(__nv_bfloat162*)(sA + phys + 4) = __floats2bfloat162_rn(f.z, f.w);
    }

    for (int oc = 0; oc < nchunks; ++oc) {
        char* sWc = sW + (oc & 1) * 16384;
#pragma unroll
        for (int j = 0; j < 8; ++j) {
            int dd = j * 4 + (tid >> 6);
            int cb = wcq * 8;
            int phys = dd * 512 + ((((cb & ~15) ^ ((dd & 7) << 4))) | (cb & 15));
            *(__nv_bfloat162*)(sWc + phys)     = __floats2bfloat162_rn(wreg[j].x, wreg[j].y);
            *(__nv_bfloat162*)(sWc + phys + 4) = __floats2bfloat162_rn(wreg[j].z, wreg[j].w);
        }
        if (oc + 1 < nchunks) {
#pragma unroll
            for (int j = 0; j < 8; ++j)
                wreg[j] = *(const float4*)(W + (size_t)((oc + 1) * 32 + j * 4 + (tid >> 6)) * CCH + wcq * 4);
        }
        __syncthreads();

        float acc[2][4] = {{0.f,0.f,0.f,0.f},{0.f,0.f,0.f,0.f}};
#pragma unroll
        for (int ks = 0; ks < 16; ++ks) {
            uint32_t aA[4], bw[4];
            int crow = ks * 16 + (l & 7) + ((l & 16) ? 8 : 0);
            int nb   = wr * 32 + ((l & 8) ? 16 : 0);
            ldsm_x4_t(aA, smem_u32(sA + crow * 128 + (nb ^ ((crow & 7) << 4))));
            int dd = wc * 16 + (l & 7) + ((l & 16) ? 8 : 0);
            int cb = ks * 32 + ((l & 8) ? 16 : 0);
            ldsm_x4(bw, smem_u32(sWc + dd * 512 + (cb ^ ((dd & 7) << 4))));
            mma_bf16(acc[0], aA, bw);
            mma_bf16(acc[1], aA, bw + 2);
        }

        int nloc = wr * 16 + (l >> 2);
        int dloc = wc * 16 + 2 * (l & 3);
#pragma unroll
        for (int t = 0; t < 2; ++t) {
            int d = oc * 32 + dloc + t * 8;
            float b0 = bias[d], b1 = bias[d + 1];
            *(__nv_bfloat162*)(dst + ((size_t)(b * NTOK + n0 + nloc) * dstw + d)) =
                __floats2bfloat162_rn((acc[t][0] + b0) * osc, (acc[t][1] + b1) * osc);
            *(__nv_bfloat162*)(dst + ((size_t)(b * NTOK + n0 + nloc + 8) * dstw + d)) =
                __floats2bfloat162_rn((acc[t][2] + b0) * osc, (acc[t][3] + b1) * osc);
        }
    }
}

// ===================== flash attention kernel =====================
// M=64 tile, 256 thr = 8 warps = 2 rowgroups x 4 key/ch-groups, OCC 2.
// Nk=32 keys/iter, 128 iters, ONE barrier/iter, QK(it+1) fused into PV(it).
// smem: Q 4K | K 3x2K | V 3x16K | P 2x4K | sums 1K = 67KB (2 CTAs/SM)
#define SQ_OFF 0
#define SK_OFF 4096
#define SV_OFF 10240
#define SP_OFF 59392
#define SS_OFF 67584
#define FLASH_SMEM 68608

__device__ __forceinline__ void load_kv(char* smem, int st,
                                        const __nv_bfloat16* kp,
                                        const __nv_bfloat16* vp,
                                        int n0k, int tid) {
    char* sK = smem + SK_OFF + st * 2048;
    char* sV = smem + SV_OFF + st * 16384;
    if (tid < 128) {   // K: 32 rows x 64B
        int n = tid >> 2, cc = tid & 3;
        cp16(smem_u32(sK + n * 64 + ((cc * 16) ^ (((n >> 1) & 3) << 4))),
             kp + (size_t)(n0k + n) * DQK + cc * 8);
    }
#pragma unroll
    for (int j = 0; j < 4; ++j) {   // V: 32 key rows x 512B
        int id = j * 256 + tid;
        int kk = id >> 5, c16 = id & 31;
        cp16(smem_u32(sV + kk * 512 + ((c16 * 16) ^ ((kk & 7) << 4))),
             vp + (size_t)(n0k + kk) * CCH + c16 * 8);
    }
}

// QK(0) prologue version: 8 keys/warp (key-split 4 ways), exp, P store (64B rows)
__device__ __forceinline__ void qk_store(char* smem, int stage, char* sPdst,
                                         const uint32_t (&aq)[2][2][4],
                                         float (&li)[2][2],
                                         int wr, int wkc, int l) {
    char* cK = smem + SK_OFF + stage * 2048;
    uint32_t bk[4];
    int n  = wkc * 8 + (l & 7);
    int cb = (l >> 3) << 4;
    ldsm_x4(bk, smem_u32(cK + n * 64 + (cb ^ (((n >> 1) & 3) << 4))));
#pragma unroll
    for (int mt = 0; mt < 2; ++mt) {
        float s[4] = {0.f, 0.f, 0.f, 0.f};
        mma_bf16(s, aq[mt][0], bk);
        mma_bf16(s, aq[mt][1], bk + 2);
        s[0] = ex2f(s[0]); s[1] = ex2f(s[1]);
        s[2] = ex2f(s[2]); s[3] = ex2f(s[3]);
        li[mt][0] += s[0] + s[1];
        li[mt][1] += s[2] + s[3];
        int R0 = wr * 32 + mt * 16 + (l >> 2), R1 = R0 + 8;
        int kb = wkc * 16 + 4 * (l & 3);
        int hi = kb & ~15, lo = kb & 15;
        *(uint32_t*)(sPdst + R0 * 64 + ((hi ^ (((R0 >> 1) & 3) << 4)) | lo)) =
            packbf(s[0], s[1]);
        *(uint32_t*)(sPdst + R1 * 64 + ((hi ^ (((R1 >> 1) & 3) << 4)) | lo)) =
            packbf(s[2], s[3]);
    }
}

__global__ void __launch_bounds__(256, 2)
flash_kernel(const float* __restrict__ zin, float* __restrict__ out) {
    extern __shared__ char smem[];
    char*  sQ   = smem + SQ_OFF;
    float* sSum = (float*)(smem + SS_OFF);

    const int b = blockIdx.y, m0 = blockIdx.x * 64;
    const int tid = threadIdx.x, l = tid & 31, wid = tid >> 5;
    const int wr  = wid >> 2;      // 0..1 : 32-query rowgroup
    const int wkc = wid & 3;       // 0..3 : keygroup (QK) / chgroup (PV)

    const __nv_bfloat16* qp = g_q + (size_t)b * NTOK * DQK;
    const __nv_bfloat16* kp = g_k + (size_t)b * NTOK * DQK;
    const __nv_bfloat16* vp = g_v + (size_t)b * NTOK * CCH;

    {   // Q tile: 64 rows x 64B
        int m = tid >> 2, cc = tid & 3;
        cp16(smem_u32(sQ + m * 64 + ((cc * 16) ^ (((m >> 1) & 3) << 4))),
             qp + (size_t)(m0 + m) * DQK + cc * 8);
    }
    load_kv(smem, 0, kp, vp, 0, tid);
    cp_commit();                    // G0: Q + stage0
    load_kv(smem, 1, kp, vp, 32, tid);
    cp_commit();                    // G1: stage1
    cp_wait<1>();                   // G0 done
    __syncthreads();

    uint32_t aq[2][2][4];
#pragma unroll
    for (int mt = 0; mt < 2; ++mt)
#pragma unroll
        for (int ks = 0; ks < 2; ++ks) {
            int row = wr * 32 + mt * 16 + (l & 15);
            int cb  = ks * 32 + ((l & 16) ? 16 : 0);
            ldsm_x4(aq[mt][ks], smem_u32(sQ + row * 64 + (cb ^ (((row >> 1) & 3) << 4))));
        }

    float o[2][8][4];
#pragma unroll
    for (int mt = 0; mt < 2; ++mt)
#pragma unroll
        for (int nt = 0; nt < 8; ++nt) { o[mt][nt][0]=0.f; o[mt][nt][1]=0.f; o[mt][nt][2]=0.f; o[mt][nt][3]=0.f; }
    float li[2][2] = {{0.f, 0.f}, {0.f, 0.f}};

    // QK(0) into P buf0
    qk_store(smem, 0, smem + SP_OFF, aq, li, wr, wkc, l);

    const int qkR0base = wr * 32 + (l >> 2);
    const int qkKb     = wkc * 16 + 4 * (l & 3);
    const int qkN      = wkc * 8 + (l & 7);
    const int qkCb     = (l >> 3) << 4;

#pragma unroll 1
    for (int it = 0; it < 128; ++it) {
        __syncthreads();   // P(it) visible; recycled-buffer readers done

        if (it + 2 < 128) load_kv(smem, (it + 2) % 3, kp, vp, (it + 2) * 32, tid);
        cp_commit();
        cp_wait<1>();      // stage(it+1) resident

        char* cV  = smem + SV_OFF + (it % 3) * 16384;
        char* sPc = smem + SP_OFF + (it & 1) * 4096;
        char* cK1 = smem + SK_OFF + ((it + 1) % 3) * 2048;
        char* sPn = smem + SP_OFF + ((it + 1) & 1) * 4096;
        const bool doqk = (it + 1 < 128);

        uint32_t bk[4];
        // ---- fused: PV(it) chunk j (16 keys) + QK(it+1) piece mt=j ----
#pragma unroll
        for (int j = 0; j < 2; ++j) {
            uint32_t pA[2][4];
#pragma unroll
            for (int mt = 0; mt < 2; ++mt) {
                int row = wr * 32 + mt * 16 + (l & 15);
                int cb  = j * 32 + ((l & 16) ? 16 : 0);
                ldsm_x4(pA[mt], smem_u32(sPc + row * 64 + (cb ^ (((row >> 1) & 3) << 4))));
            }
            uint32_t bv[4];
            {
                int rowv  = j * 16 + (l & 15);
                int cbyte = wkc * 128 + ((l & 16) ? 16 : 0);
                ldsm_x4_t(bv, smem_u32(cV + rowv * 512 + (cbyte ^ ((rowv & 7) << 4))));
            }
#pragma unroll
            for (int ct = 0; ct < 4; ++ct) {
                uint32_t bvn[4];
                if (ct < 3) {
                    int rowv  = j * 16 + (l & 15);
                    int cbyte = wkc * 128 + (ct + 1) * 32 + ((l & 16) ? 16 : 0);
                    ldsm_x4_t(bvn, smem_u32(cV + rowv * 512 + (cbyte ^ ((rowv & 7) << 4))));
                }
#pragma unroll
                for (int mt = 0; mt < 2; ++mt) {
                    mma_bf16(o[mt][ct * 2],     pA[mt], bv);
                    mma_bf16(o[mt][ct * 2 + 1], pA[mt], bv + 2);
                }
                if (ct < 3) { bv[0]=bvn[0]; bv[1]=bvn[1]; bv[2]=bvn[2]; bv[3]=bvn[3]; }
            }

            if (doqk) {
                const int mt = j;
                if (j == 0)
                    ldsm_x4(bk, smem_u32(cK1 + qkN * 64 + (qkCb ^ (((qkN >> 1) & 3) << 4))));
                float s[4] = {0.f, 0.f, 0.f, 0.f};
                mma_bf16(s, aq[mt][0], bk);
                mma_bf16(s, aq[mt][1], bk + 2);
                s[0] = ex2f(s[0]); s[1] = ex2f(s[1]);
                s[2] = ex2f(s[2]); s[3] = ex2f(s[3]);
                li[mt][0] += s[0] + s[1];
                li[mt][1] += s[2] + s[3];
                int R0 = qkR0base + mt * 16, R1 = R0 + 8;
                int hi = qkKb & ~15, lo = qkKb & 15;
                *(uint32_t*)(sPn + R0 * 64 + ((hi ^ (((R0 >> 1) & 3) << 4)) | lo)) =
                    packbf(s[0], s[1]);
                *(uint32_t*)(sPn + R1 * 64 + ((hi ^ (((R1 >> 1) & 3) << 4)) | lo)) =
                    packbf(s[2], s[3]);
            }
        }
    }

    // ---- epilogue: cross-warp row-sum reduction ----
#pragma unroll
    for (int mt = 0; mt < 2; ++mt)
#pragma unroll
        for (int h = 0; h < 2; ++h) {
            li[mt][h] += __shfl_xor_sync(0xffffffffu, li[mt][h], 1);
            li[mt][h] += __shfl_xor_sync(0xffffffffu, li[mt][h], 2);
        }
    if ((l & 3) == 0) {
#pragma unroll
        for (int mt = 0; mt < 2; ++mt)
#pragma unroll
            for (int h = 0; h < 2; ++h)
                sSum[(wr * 32 + mt * 16 + h * 8 + (l >> 2)) * 4 + wkc] = li[mt][h];
    }
    __syncthreads();

#pragma unroll
    for (int mt = 0; mt < 2; ++mt) {
        int r0 = wr * 32 + mt * 16 + (l >> 2);
        float4 s0 = *(float4*)(sSum + r0 * 4);
        float4 s1 = *(float4*)(sSum + (r0 + 8) * 4);
        float i0 = 1.f / (s0.x + s0.y + s0.z + s0.w);
        float i1 = 1.f / (s1.x + s1.y + s1.z + s1.w);
        int tok = m0 + r0;
#pragma unroll
        for (int nt = 0; nt < 8; ++nt) {
            int ch = wkc * 64 + nt * 8 + 2 * (l & 3);
            size_t base0 = ((size_t)(b * CCH + ch)) * NTOK + tok;
            size_t base1 = base0 + NTOK;
            out[base0]     = zin[base0]     + o[mt][nt][0] * i0;
            out[base1]     = zin[base1]     + o[mt][nt][1] * i0;
            out[base0 + 8] = zin[base0 + 8] + o[mt][nt][2] * i1;
            out[base1 + 8] = zin[base1 + 8] + o[mt][nt][3] * i1;
        }
    }
}

extern "C" void kernel_launch(void* const* d_in, const int* in_sizes, int n_in,
                              void* d_out, int out_size) {
    const float* z  = (const float*)d_in[0];
    const float* x  = (const float*)d_in[1];
    const float* y  = (const float*)d_in[2];
    const float* Wq = (const float*)d_in[3];
    const float* bq = (const float*)d_in[4];
    const float* Wk = (const float*)d_in[5];
    const float* bk = (const float*)d_in[6];
    const float* Wv = (const float*)d_in[7];
    const float* bv = (const float*)d_in[8];
    float* out = (float*)d_out;

    cudaFuncSetAttribute(proj_kernel, cudaFuncAttributeMaxDynamicSharedMemorySize,
                         PROJ_SMEM);
    cudaFuncSetAttribute(flash_kernel, cudaFuncAttributeMaxDynamicSharedMemorySize,
                         FLASH_SMEM);

    proj_kernel<<<dim3(64, 4, 3), 256, PROJ_SMEM>>>(z, x, y, Wq, bq, Wk, bk, Wv, bv);
    flash_kernel<<<dim3(64, 4), 256, FLASH_SMEM>>>(z, out);
}

// round 16
// speedup vs baseline: 1.1006x; 1.1006x over previous
#include <cuda_runtime.h>
#include <cuda_bf16.h>
#include <cstdint>

#define BATCH 4
#define CCH   256
#define DQK   32
#define NTOK  4096

__device__ __nv_bfloat16 g_q[BATCH * NTOK * DQK];
__device__ __nv_bfloat16 g_k[BATCH * NTOK * DQK];
__device__ __nv_bfloat16 g_v[BATCH * NTOK * CCH];   // token-major [B,N,C]

__device__ __forceinline__ uint32_t smem_u32(const void* p) {
    return (uint32_t)__cvta_generic_to_shared(p);
}
__device__ __forceinline__ void cp16(uint32_t dst, const void* src) {
    asm volatile("cp.async.cg.shared.global [%0], [%1], 16;\n" :: "r"(dst), "l"(src));
}
__device__ __forceinline__ void cp_commit() { asm volatile("cp.async.commit_group;\n"); }
template <int N> __device__ __forceinline__ void cp_wait() {
    asm volatile("cp.async.wait_group %0;\n" :: "n"(N));
}
__device__ __forceinline__ void ldsm_x4(uint32_t* r, uint32_t a) {
    asm volatile("ldmatrix.sync.aligned.m8n8.x4.shared.b16 {%0,%1,%2,%3}, [%4];\n"
                 : "=r"(r[0]), "=r"(r[1]), "=r"(r[2]), "=r"(r[3]) : "r"(a));
}
__device__ __forceinline__ void ldsm_x4_t(uint32_t* r, uint32_t a) {
    asm volatile("ldmatrix.sync.aligned.m8n8.x4.trans.shared.b16 {%0,%1,%2,%3}, [%4];\n"
                 : "=r"(r[0]), "=r"(r[1]), "=r"(r[2]), "=r"(r[3]) : "r"(a));
}
__device__ __forceinline__ void mma_bf16(float* c, const uint32_t* a, const uint32_t* b) {
    asm volatile(
        "mma.sync.aligned.m16n8k16.row.col.f32.bf16.bf16.f32 "
        "{%0,%1,%2,%3}, {%4,%5,%6,%7}, {%8,%9}, {%0,%1,%2,%3};\n"
        : "+f"(c[0]), "+f"(c[1]), "+f"(c[2]), "+f"(c[3])
        : "r"(a[0]), "r"(a[1]), "r"(a[2]), "r"(a[3]), "r"(b[0]), "r"(b[1]));
}
__device__ __forceinline__ uint32_t packbf(float a, float b) {
    __nv_bfloat162 h = __floats2bfloat162_rn(a, b);
    return reinterpret_cast<uint32_t&>(h);
}
__device__ __forceinline__ float ex2f(float x) {
    float y; asm("ex2.approx.ftz.f32 %0, %1;" : "=f"(y) : "f"(x)); return y;
}

// ===================== projection kernel =====================
// grid (64, 4, 4): z=0 -> V chunks 0-3, z=1 -> V chunks 4-7 (heavy CTAs
// launch FIRST), z=2 -> Q, z=3 -> K. W double-buffered, register-prefetched.
#define PROJ_SMEM (32768 + 32768)

__global__ void __launch_bounds__(256, 2)
proj_kernel(const float* __restrict__ zin, const float* __restrict__ xin,
            const float* __restrict__ yin,
            const float* __restrict__ Wq, const float* __restrict__ bq,
            const float* __restrict__ Wk, const float* __restrict__ bk,
            const float* __restrict__ Wv, const float* __restrict__ bv) {
    extern __shared__ char smem[];
    char* sA = smem;            // [c=256][128B] bf16 swizzled
    char* sW = smem + 32768;    // 2 x [d=32][512B] bf16 swizzled

    const int sel = blockIdx.z, b = blockIdx.y, n0 = blockIdx.x * 64;
    const int tid = threadIdx.x, l = tid & 31, wid = tid >> 5;
    const int wr = wid >> 1, wc = wid & 1;

    const bool isv = (sel < 2);
    const float* src  = isv ? zin : ((sel == 2) ? xin : yin);
    const float* W    = isv ? Wv  : ((sel == 2) ? Wq  : Wk);
    const float* bias = isv ? bv  : ((sel == 2) ? bq  : bk);
    __nv_bfloat16* dst = isv ? g_v : ((sel == 2) ? g_q : g_k);
    const int dstw    = isv ? CCH : DQK;
    const int nchunks = isv ? 4 : 1;
    const int ocbase  = isv ? sel * 4 : 0;
    const float osc   = (sel == 2) ? 1.44269504f : 1.0f;   // fold log2(e) into q

    const int wcq = tid & 63;

    // prologue: first W chunk into registers
    float4 wreg[8];
#pragma unroll
    for (int j = 0; j < 8; ++j)
        wreg[j] = *(const float4*)(W + (size_t)(ocbase * 32 + j * 4 + (tid >> 6)) * CCH + wcq * 4);

    // A tile: [256 c][64 n] fp32 -> bf16 smem (swizzled)
#pragma unroll
    for (int j = 0; j < 16; ++j) {
        int id = j * 256 + tid;
        int c = id >> 4, nq = id & 15;
        float4 f = *(const float4*)(src + ((size_t)(b * CCH + c) * NTOK + n0 + nq * 4));
        int nb = nq * 8;
        int phys = c * 128 + ((((nb & ~15) ^ ((c & 7) << 4))) | (nb & 15));
        *(__nv_bfloat162*)(sA + phys)     = __floats2bfloat162_rn(f.x, f.y);
        *(__nv_bfloat162*)(sA + phys + 4) = __floats2bfloat162_rn(f.z, f.w);
    }

    for (int oc = 0; oc < nchunks; ++oc) {
        const int ci = ocbase + oc;
        char* sWc = sW + (oc & 1) * 16384;
#pragma unroll
        for (int j = 0; j < 8; ++j) {
            int dd = j * 4 + (tid >> 6);
            int cb = wcq * 8;
            int phys = dd * 512 + ((((cb & ~15) ^ ((dd & 7) << 4))) | (cb & 15));
            *(__nv_bfloat162*)(sWc + phys)     = __floats2bfloat162_rn(wreg[j].x, wreg[j].y);
            *(__nv_bfloat162*)(sWc + phys + 4) = __floats2bfloat162_rn(wreg[j].z, wreg[j].w);
        }
        if (oc + 1 < nchunks) {
#pragma unroll
            for (int j = 0; j < 8; ++j)
                wreg[j] = *(const float4*)(W + (size_t)((ci + 1) * 32 + j * 4 + (tid >> 6)) * CCH + wcq * 4);
        }
        __syncthreads();   // sA (first iter) + sWc ready; prior compute done

        float acc[2][4] = {{0.f,0.f,0.f,0.f},{0.f,0.f,0.f,0.f}};
#pragma unroll
        for (int ks = 0; ks < 16; ++ks) {
            uint32_t aA[4], bw[4];
            int crow = ks * 16 + (l & 7) + ((l & 16) ? 8 : 0);
            int nb   = wr * 32 + ((l & 8) ? 16 : 0);
            ldsm_x4_t(aA, smem_u32(sA + crow * 128 + (nb ^ ((crow & 7) << 4))));
            int dd = wc * 16 + (l & 7) + ((l & 16) ? 8 : 0);
            int cb = ks * 32 + ((l & 8) ? 16 : 0);
            ldsm_x4(bw, smem_u32(sWc + dd * 512 + (cb ^ ((dd & 7) << 4))));
            mma_bf16(acc[0], aA, bw);
            mma_bf16(acc[1], aA, bw + 2);
        }

        int nloc = wr * 16 + (l >> 2);
        int dloc = wc * 16 + 2 * (l & 3);
#pragma unroll
        for (int t = 0; t < 2; ++t) {
            int d = ci * 32 + dloc + t * 8;
            float b0 = bias[d], b1 = bias[d + 1];
            *(__nv_bfloat162*)(dst + ((size_t)(b * NTOK + n0 + nloc) * dstw + d)) =
                __floats2bfloat162_rn((acc[t][0] + b0) * osc, (acc[t][1] + b1) * osc);
            *(__nv_bfloat162*)(dst + ((size_t)(b * NTOK + n0 + nloc + 8) * dstw + d)) =
                __floats2bfloat162_rn((acc[t][2] + b0) * osc, (acc[t][3] + b1) * osc);
        }
    }
}

// ===================== flash attention kernel (R13 best: 120.2us) =====================
#define SQ_OFF 0
#define SK_OFF 8192
#define SV_OFF 20480
#define SP_OFF 118784
#define SS_OFF 151552
#define FLASH_SMEM 153600

__device__ __forceinline__ void load_kv(char* smem, int st,
                                        const __nv_bfloat16* kp,
                                        const __nv_bfloat16* vp,
                                        int n0k, int tid) {
    char* sK = smem + SK_OFF + st * 4096;
    char* sV = smem + SV_OFF + st * 32768;
    if (tid < 256) {   // K: 64 rows x 64B
        int n = tid >> 2, cc = tid & 3;
        cp16(smem_u32(sK + n * 64 + ((cc * 16) ^ (((n >> 1) & 3) << 4))),
             kp + (size_t)(n0k + n) * DQK + cc * 8);
    }
#pragma unroll
    for (int j = 0; j < 4; ++j) {   // V: 64 key rows x 512B
        int id = j * 512 + tid;
        int kk = id >> 5, c16 = id & 31;
        cp16(smem_u32(sV + kk * 512 + ((c16 * 16) ^ ((kk & 7) << 4))),
             vp + (size_t)(n0k + kk) * CCH + c16 * 8);
    }
}

__device__ __forceinline__ void qk_store(char* smem, int stage, char* sPdst,
                                         const uint32_t (&aq)[2][2][4],
                                         float (&li)[2][2],
                                         int wr, int wkc, int l) {
    char* cK = smem + SK_OFF + stage * 4096;
#pragma unroll
    for (int nt = 0; nt < 2; ++nt) {
        uint32_t bk[4];
        int n  = wkc * 16 + nt * 8 + (l & 7);
        int cb = (l >> 3) << 4;
        ldsm_x4(bk, smem_u32(cK + n * 64 + (cb ^ (((n >> 1) & 3) << 4))));
#pragma unroll
        for (int mt = 0; mt < 2; ++mt) {
            float s[4] = {0.f, 0.f, 0.f, 0.f};
            mma_bf16(s, aq[mt][0], bk);
            mma_bf16(s, aq[mt][1], bk + 2);
            s[0] = ex2f(s[0]); s[1] = ex2f(s[1]);
            s[2] = ex2f(s[2]); s[3] = ex2f(s[3]);
            li[mt][0] += s[0] + s[1];
            li[mt][1] += s[2] + s[3];
            int R0 = wr * 32 + mt * 16 + (l >> 2), R1 = R0 + 8;
            int kb = wkc * 32 + nt * 16 + 4 * (l & 3);
            int hi = kb & ~15, lo = kb & 15;
            *(uint32_t*)(sPdst + R0 * 128 + ((hi ^ ((R0 & 7) << 4)) | lo)) =
                packbf(s[0], s[1]);
            *(uint32_t*)(sPdst + R1 * 128 + ((hi ^ ((R1 & 7) << 4)) | lo)) =
                packbf(s[2], s[3]);
        }
    }
}

__global__ void __launch_bounds__(512, 1)
flash_kernel(const float* __restrict__ zin, float* __restrict__ out) {
    extern __shared__ char smem[];
    char*  sQ   = smem + SQ_OFF;
    float* sSum = (float*)(smem + SS_OFF);

    const int b = blockIdx.y, m0 = blockIdx.x * 128;
    const int tid = threadIdx.x, l = tid & 31, wid = tid >> 5;
    const int wr  = wid >> 2;
    const int wkc = wid & 3;

    const __nv_bfloat16* qp = g_q + (size_t)b * NTOK * DQK;
    const __nv_bfloat16* kp = g_k + (size_t)b * NTOK * DQK;
    const __nv_bfloat16* vp = g_v + (size_t)b * NTOK * CCH;

    {
        int m = tid >> 2, cc = tid & 3;
        cp16(smem_u32(sQ + m * 64 + ((cc * 16) ^ (((m >> 1) & 3) << 4))),
             qp + (size_t)(m0 + m) * DQK + cc * 8);
    }
    load_kv(smem, 0, kp, vp, 0, tid);
    cp_commit();
    load_kv(smem, 1, kp, vp, 64, tid);
    cp_commit();
    cp_wait<1>();
    __syncthreads();

    uint32_t aq[2][2][4];
#pragma unroll
    for (int mt = 0; mt < 2; ++mt)
#pragma unroll
        for (int ks = 0; ks < 2; ++ks) {
            int row = wr * 32 + mt * 16 + (l & 15);
            int cb  = ks * 32 + ((l & 16) ? 16 : 0);
            ldsm_x4(aq[mt][ks], smem_u32(sQ + row * 64 + (cb ^ (((row >> 1) & 3) << 4))));
        }

    float o[2][8][4];
#pragma unroll
    for (int mt = 0; mt < 2; ++mt)
#pragma unroll
        for (int nt = 0; nt < 8; ++nt) { o[mt][nt][0]=0.f; o[mt][nt][1]=0.f; o[mt][nt][2]=0.f; o[mt][nt][3]=0.f; }
    float li[2][2] = {{0.f, 0.f}, {0.f, 0.f}};

    qk_store(smem, 0, smem + SP_OFF, aq, li, wr, wkc, l);

    const int qkR0base = wr * 32 + (l >> 2);
    const int qkKbase  = wkc * 32 + 4 * (l & 3);
    const int qkNbase  = wkc * 16 + (l & 7);
    const int qkCb     = (l >> 3) << 4;

#pragma unroll 1
    for (int it = 0; it < 64; ++it) {
        __syncthreads();

        if (it + 2 < 64) load_kv(smem, (it + 2) % 3, kp, vp, (it + 2) * 64, tid);
        cp_commit();
        cp_wait<1>();

        char* cV  = smem + SV_OFF + (it % 3) * 32768;
        char* sPc = smem + SP_OFF + (it & 1) * 16384;
        char* cK1 = smem + SK_OFF + ((it + 1) % 3) * 4096;
        char* sPn = smem + SP_OFF + ((it + 1) & 1) * 16384;
        const bool doqk = (it + 1 < 64);

        uint32_t bk[4];
#pragma unroll
        for (int j = 0; j < 4; ++j) {
            uint32_t pA[2][4];
#pragma unroll
            for (int mt = 0; mt < 2; ++mt) {
                int row = wr * 32 + mt * 16 + (l & 15);
                int cb  = j * 32 + ((l & 16) ? 16 : 0);
                ldsm_x4(pA[mt], smem_u32(sPc + row * 128 + (cb ^ ((row & 7) << 4))));
            }
            uint32_t bv[4];
            {
                int rowv  = j * 16 + (l & 15);
                int cbyte = wkc * 128 + ((l & 16) ? 16 : 0);
                ldsm_x4_t(bv, smem_u32(cV + rowv * 512 + (cbyte ^ ((rowv & 7) << 4))));
            }
#pragma unroll
            for (int ct = 0; ct < 4; ++ct) {
                uint32_t bvn[4];
                if (ct < 3) {
                    int rowv  = j * 16 + (l & 15);
                    int cbyte = wkc * 128 + (ct + 1) * 32 + ((l & 16) ? 16 : 0);
                    ldsm_x4_t(bvn, smem_u32(cV + rowv * 512 + (cbyte ^ ((rowv & 7) << 4))));
                }
#pragma unroll
                for (int mt = 0; mt < 2; ++mt) {
                    mma_bf16(o[mt][ct * 2],     pA[mt], bv);
                    mma_bf16(o[mt][ct * 2 + 1], pA[mt], bv + 2);
                }
                if (ct < 3) { bv[0]=bvn[0]; bv[1]=bvn[1]; bv[2]=bvn[2]; bv[3]=bvn[3]; }
            }

            if (doqk) {
                const int nt = j >> 1, mt = j & 1;
                if ((j & 1) == 0) {
                    int n = qkNbase + nt * 8;
                    ldsm_x4(bk, smem_u32(cK1 + n * 64 + (qkCb ^ (((n >> 1) & 3) << 4))));
                }
                float s[4] = {0.f, 0.f, 0.f, 0.f};
                mma_bf16(s, aq[mt][0], bk);
                mma_bf16(s, aq[mt][1], bk + 2);
                s[0] = ex2f(s[0]); s[1] = ex2f(s[1]);
                s[2] = ex2f(s[2]); s[3] = ex2f(s[3]);
                li[mt][0] += s[0] + s[1];
                li[mt][1] += s[2] + s[3];
                int R0 = qkR0base + mt * 16, R1 = R0 + 8;
                int kb = qkKbase + nt * 16;
                int hi = kb & ~15, lo = kb & 15;
                *(uint32_t*)(sPn + R0 * 128 + ((hi ^ ((R0 & 7) << 4)) | lo)) =
                    packbf(s[0], s[1]);
                *(uint32_t*)(sPn + R1 * 128 + ((hi ^ ((R1 & 7) << 4)) | lo)) =
                    packbf(s[2], s[3]);
            }
        }
    }

#pragma unroll
    for (int mt = 0; mt < 2; ++mt)
#pragma unroll
        for (int h = 0; h < 2; ++h) {
            li[mt][h] += __shfl_xor_sync(0xffffffffu, li[mt][h], 1);
            li[mt][h] += __shfl_xor_sync(0xffffffffu, li[mt][h], 2);
        }
    if ((l & 3) == 0) {
#pragma unroll
        for (int mt = 0; mt < 2; ++mt)
#pragma unroll
            for (int h = 0; h < 2; ++h)
                sSum[(wr * 32 + mt * 16 + h * 8 + (l >> 2)) * 4 + wkc] = li[mt][h];
    }
    __syncthreads();

#pragma unroll
    for (int mt = 0; mt < 2; ++mt) {
        int r0 = wr * 32 + mt * 16 + (l >> 2);
        float4 s0 = *(float4*)(sSum + r0 * 4);
        float4 s1 = *(float4*)(sSum + (r0 + 8) * 4);
        float i0 = 1.f / (s0.x + s0.y + s0.z + s0.w);
        float i1 = 1.f / (s1.x + s1.y + s1.z + s1.w);
        int tok = m0 + r0;
#pragma unroll
        for (int nt = 0; nt < 8; ++nt) {
            int ch = wkc * 64 + nt * 8 + 2 * (l & 3);
            size_t base0 = ((size_t)(b * CCH + ch)) * NTOK + tok;
            size_t base1 = base0 + NTOK;
            out[base0]     = zin[base0]     + o[mt][nt][0] * i0;
            out[base1]     = zin[base1]     + o[mt][nt][1] * i0;
            out[base0 + 8] = zin[base0 + 8] + o[mt][nt][2] * i1;
            out[base1 + 8] = zin[base1 + 8] + o[mt][nt][3] * i1;
        }
    }
}

extern "C" void kernel_launch(void* const* d_in, const int* in_sizes, int n_in,
                              void* d_out, int out_size) {
    const float* z  = (const float*)d_in[0];
    const float* x  = (const float*)d_in[1];
    const float* y  = (const float*)d_in[2];
    const float* Wq = (const float*)d_in[3];
    const float* bq = (const float*)d_in[4];
    const float* Wk = (const float*)d_in[5];
    const float* bk = (const float*)d_in[6];
    const float* Wv = (const float*)d_in[7];
    const float* bv = (const float*)d_in[8];
    float* out = (float*)d_out;

    cudaFuncSetAttribute(proj_kernel, cudaFuncAttributeMaxDynamicSharedMemorySize,
                         PROJ_SMEM);
    cudaFuncSetAttribute(flash_kernel, cudaFuncAttributeMaxDynamicSharedMemorySize,
                         FLASH_SMEM);

    proj_kernel<<<dim3(64, 4, 4), 256, PROJ_SMEM>>>(z, x, y, Wq, bq, Wk, bk, Wv, bv);
    flash_kernel<<<dim3(32, 4), 512, FLASH_SMEM>>>(z, out);
}